// round 13
// baseline (speedup 1.0000x reference)
#include <cuda_runtime.h>
#include <cuda_fp16.h>
#include <cstdint>

// ---------------- problem constants ----------------
#define BB     8
#define NN     8192
#define CIN    32
#define COUT   32
#define NS     2
#define JCOLS  256        // B * C_OUT

// ---------------- GEMM tiling ----------------
#define BM     128
#define BN     256        // full J width
#define BK     32
#define NSTAGE 5
#define NKT    (NN / BK)  // 256

#define PADWF  36                       // f32 A stage row stride (words)
#define PADH   40                       // fp16 row stride (halves): 80B, LDSM conflict-free
#define AF32_STG_B  (BM * PADWF * 4)    // 18432 B / stage
#define B16_STG_B   (BN * PADH * 2)     // 20480 B / stage
#define A16_BUF_B   (BM * PADH * 2)     // 10240 B / buffer
#define AF32_OFF    0
#define B16_OFF     (NSTAGE * AF32_STG_B)                 // 92160
#define A16_OFF     (B16_OFF + NSTAGE * B16_STG_B)        // 194560
#define SMEM_BYTES  (A16_OFF + 2 * A16_BUF_B)             // 215040

// ---------------- scratch ----------------
__device__ __align__(1024) __half g_yt16[(size_t)NS * JCOLS * NN];   // [s][j][m] fp16
__device__ __align__(1024) float  g_part[(size_t)NS * NN * JCOLS];   // [s][n][j]

// ---------------- PTX helpers (<= sm_80 base features only) ----------------
static __device__ __forceinline__ uint32_t smem_u32(const void* p) {
    uint32_t a;
    asm("{ .reg .u64 t; cvta.to.shared.u64 t, %1; cvt.u32.u64 %0, t; }" : "=r"(a) : "l"(p));
    return a;
}
#define CP16(dst, src) \
    asm volatile("cp.async.cg.shared.global [%0], [%1], 16;" :: "r"(dst), "l"(src) : "memory")
#define CPCOMMIT() asm volatile("cp.async.commit_group;" ::: "memory")
#define CPWAIT(n)  asm volatile("cp.async.wait_group %0;" :: "n"(n) : "memory")

#define LDSM_X4(r0, r1, r2, r3, addr) \
    asm volatile("ldmatrix.sync.aligned.m8n8.x4.shared.b16 {%0,%1,%2,%3}, [%4];" \
                 : "=r"(r0), "=r"(r1), "=r"(r2), "=r"(r3) : "r"(addr))

#define MMA_F16(d, a, b) \
    asm volatile("mma.sync.aligned.m16n8k16.row.col.f32.f16.f16.f32 " \
                 "{%0,%1,%2,%3}, {%4,%5,%6,%7}, {%8,%9}, {%0,%1,%2,%3};" \
                 : "+f"((d)[0]), "+f"((d)[1]), "+f"((d)[2]), "+f"((d)[3]) \
                 : "r"((a)[0]), "r"((a)[1]), "r"((a)[2]), "r"((a)[3]), \
                   "r"((b)[0]), "r"((b)[1]))

// ---- kernel 1: Yt[s][j][m] = sum_c x[b][m][c]*W[s][o][c]  (fp16-RN output) ----
#define YT_XS_W   (BB * 32 * CIN)          // 8192 floats
#define YT_WS_W   (COUT * 33)              // 1056 floats
#define YT_OUT_H  (JCOLS * 34)             // 8704 halves
#define YT_SMEM   ((YT_XS_W + YT_WS_W) * 4 + YT_OUT_H * 2)   // 54400 B

__global__ void __launch_bounds__(256) yt_kernel(const float* __restrict__ x,
                                                 const float* __restrict__ W) {
    extern __shared__ float sm[];
    float* xs = sm;                          // [b][m][c]
    float* ws = sm + YT_XS_W;                // [o][33]
    __half* outs = (__half*)(ws + YT_WS_W);  // [j][34]
    int s  = blockIdx.y;
    int m0 = blockIdx.x * 32;
    int t  = threadIdx.x;

    for (int i = t; i < COUT * CIN; i += 256)
        ws[(i >> 5) * 33 + (i & 31)] = W[s * COUT * CIN + i];
    for (int i = t; i < YT_XS_W; i += 256) {
        int b = i >> 10;
        xs[i] = x[(size_t)b * NN * CIN + (size_t)m0 * CIN + (i & 1023)];
    }
    __syncthreads();

    int b = t >> 5, o = t & 31;
    float wr[32];
#pragma unroll
    for (int c = 0; c < 32; ++c) wr[c] = ws[o * 33 + c];

    const float4* xr = (const float4*)(xs + b * 1024);
    __half* orow = outs + t * 34;
    for (int m = 0; m < 32; ++m) {
        float acc = 0.f;
#pragma unroll
        for (int q = 0; q < 8; ++q) {
            float4 v = xr[m * 8 + q];
            acc = fmaf(v.x, wr[q * 4 + 0], acc);
            acc = fmaf(v.y, wr[q * 4 + 1], acc);
            acc = fmaf(v.z, wr[q * 4 + 2], acc);
            acc = fmaf(v.w, wr[q * 4 + 3], acc);
        }
        orow[m] = __float2half_rn(acc);
    }
    __syncthreads();

    uint32_t* dst32 = (uint32_t*)g_yt16;
    for (int i = t; i < JCOLS * 16; i += 256) {
        int j = i >> 4, mp = i & 15;
        uint32_t v = *(const uint32_t*)(outs + j * 34 + 2 * mp);
        dst32[((((size_t)s * JCOLS + j) * NN + m0) >> 1) + mp] = v;
    }
}

// ---- kernel 2: fp16 GEMM, pipelined in-kernel A conversion ----
__global__ void __launch_bounds__(256, 1) gemm_kernel(const float* __restrict__ supports) {
    extern __shared__ char smc[];
    int tid  = threadIdx.x;
    int lane = tid & 31, w = tid >> 5;
    int wm = w >> 2, wn = w & 3;              // 2 (M) x 4 (N) warp grid, 64x64 each
    int n0 = blockIdx.x * BM;
    int s  = blockIdx.y;

    const float*  Abase = supports + ((size_t)s * NN + n0) * NN;
    const __half* Bbase = g_yt16 + (size_t)s * JCOLS * NN;
    uint32_t smb = smem_u32(smc);

    uint32_t a_row  = (uint32_t)(lane & 15);
    uint32_t a_koff = (uint32_t)((lane >> 4) << 3);
    uint32_t b_row  = (uint32_t)((lane & 7) + ((lane >> 4) << 3));
    uint32_t b_koff = (uint32_t)(((lane >> 3) & 1) << 3);

    int cr = tid >> 1, ch = tid & 1;          // convert: 2 threads per A row

    // prologue: fill stages 0..3
#pragma unroll
    for (int p = 0; p < NSTAGE - 1; ++p) {
#pragma unroll
        for (int i = 0; i < 8; ++i) {
            int idx = i * 256 + tid;
            if (idx < 1024) {                  // A f32
                int r = idx >> 3, c = idx & 7;
                CP16(smb + AF32_OFF + p * AF32_STG_B + (uint32_t)(r * PADWF + c * 4) * 4,
                     Abase + (size_t)r * NN + (size_t)p * BK + c * 4);
            } else {                           // B fp16
                int bi = idx - 1024;
                int r = bi >> 2, c = bi & 3;
                CP16(smb + B16_OFF + p * B16_STG_B + (uint32_t)(r * PADH * 2 + c * 16),
                     Bbase + (size_t)r * NN + (size_t)p * BK + c * 8);
            }
        }
        CPCOMMIT();
    }

    float acc[4][8][4];
#pragma unroll
    for (int mt = 0; mt < 4; ++mt)
#pragma unroll
        for (int nt = 0; nt < 8; ++nt)
#pragma unroll
            for (int r = 0; r < 4; ++r) acc[mt][nt][r] = 0.f;

    // prologue convert: stage 0 -> buf 0 (published by iter-0 sync)
    CPWAIT(3);
    __syncthreads();
    {
        const float4* af = (const float4*)(smc + AF32_OFF);
        int fi = cr * (PADWF / 4) + ch * 4;
        float4 v0 = af[fi], v1 = af[fi + 1], v2 = af[fi + 2], v3 = af[fi + 3];
        __half2 h[8];
        h[0] = __floats2half2_rn(v0.x, v0.y); h[1] = __floats2half2_rn(v0.z, v0.w);
        h[2] = __floats2half2_rn(v1.x, v1.y); h[3] = __floats2half2_rn(v1.z, v1.w);
        h[4] = __floats2half2_rn(v2.x, v2.y); h[5] = __floats2half2_rn(v2.z, v2.w);
        h[6] = __floats2half2_rn(v3.x, v3.y); h[7] = __floats2half2_rn(v3.z, v3.w);
        uint4* dst = (uint4*)(smc + A16_OFF + (cr * PADH + ch * 16) * 2);
        dst[0] = *(uint4*)&h[0];
        dst[1] = *(uint4*)&h[4];
    }

    int s0 = 0;                                // kt % 5
    for (int kt = 0; kt < NKT; ++kt) {
        int s1 = (s0 == 4) ? 0 : s0 + 1;       // (kt+1) % 5
        int s4 = (s0 == 0) ? 4 : s0 - 1;       // (kt+4) % 5

        CPWAIT(2);                             // stages kt, kt+1 landed (this thread)
        __syncthreads();                       // publish stage kt+1 and buf[kt&1]

        int kn = kt + NSTAGE - 1;
        if (kn < NKT) {                        // refill slot s4 (dead since iter kt-1)
#pragma unroll
            for (int i = 0; i < 8; ++i) {
                int idx = i * 256 + tid;
                if (idx < 1024) {
                    int r = idx >> 3, c = idx & 7;
                    CP16(smb + AF32_OFF + s4 * AF32_STG_B + (uint32_t)(r * PADWF + c * 4) * 4,
                         Abase + (size_t)r * NN + (size_t)kn * BK + c * 4);
                } else {
                    int bi = idx - 1024;
                    int r = bi >> 2, c = bi & 3;
                    CP16(smb + B16_OFF + s4 * B16_STG_B + (uint32_t)(r * PADH * 2 + c * 16),
                         Bbase + (size_t)r * NN + (size_t)kn * BK + c * 8);
                }
            }
            CPCOMMIT();
        }

        // convert stage kt+1 (f32, slot s1) -> buf[(kt+1)&1]; overlaps MMAs below
        if (kt + 1 < NKT) {
            const float4* af = (const float4*)(smc + AF32_OFF + s1 * AF32_STG_B);
            int fi = cr * (PADWF / 4) + ch * 4;
            float4 v0 = af[fi], v1 = af[fi + 1], v2 = af[fi + 2], v3 = af[fi + 3];
            __half2 h[8];
            h[0] = __floats2half2_rn(v0.x, v0.y); h[1] = __floats2half2_rn(v0.z, v0.w);
            h[2] = __floats2half2_rn(v1.x, v1.y); h[3] = __floats2half2_rn(v1.z, v1.w);
            h[4] = __floats2half2_rn(v2.x, v2.y); h[5] = __floats2half2_rn(v2.z, v2.w);
            h[6] = __floats2half2_rn(v3.x, v3.y); h[7] = __floats2half2_rn(v3.z, v3.w);
            uint4* dst = (uint4*)(smc + A16_OFF + ((kt + 1) & 1) * A16_BUF_B
                                  + (cr * PADH + ch * 16) * 2);
            dst[0] = *(uint4*)&h[0];
            dst[1] = *(uint4*)&h[4];
        }

        uint32_t A16 = smb + A16_OFF + (kt & 1) * A16_BUF_B;
        uint32_t B16 = smb + B16_OFF + s0 * B16_STG_B;
#pragma unroll
        for (int kc = 0; kc < 2; ++kc) {
            uint32_t af4[4][4], bf[8][2];
#pragma unroll
            for (int mt = 0; mt < 4; ++mt) {
                uint32_t ad = A16 + (((uint32_t)(wm * 64 + mt * 16) + a_row) * PADH
                                     + kc * 16 + a_koff) * 2;
                LDSM_X4(af4[mt][0], af4[mt][1], af4[mt][2], af4[mt][3], ad);
            }
#pragma unroll
            for (int np = 0; np < 4; ++np) {
                uint32_t bd = B16 + (((uint32_t)(wn * 64 + np * 16) + b_row) * PADH
                                     + kc * 16 + b_koff) * 2;
                LDSM_X4(bf[2 * np][0], bf[2 * np][1], bf[2 * np + 1][0], bf[2 * np + 1][1], bd);
            }
#pragma unroll
            for (int mt = 0; mt < 4; ++mt)
#pragma unroll
                for (int nt = 0; nt < 8; ++nt)
                    MMA_F16(acc[mt][nt], af4[mt], bf[nt]);
        }
        s0 = s1;
    }

    // epilogue
    int g = lane >> 2, t4 = lane & 3;
    float* dst = g_part + ((size_t)s * NN + n0) * JCOLS;
#pragma unroll
    for (int mt = 0; mt < 4; ++mt) {
#pragma unroll
        for (int nt = 0; nt < 8; ++nt) {
            int row = wm * 64 + mt * 16 + g;
            int col = wn * 64 + nt * 8 + 2 * t4;
            *(float2*)(dst + (size_t)row * JCOLS + col) =
                make_float2(acc[mt][nt][0], acc[mt][nt][1]);
            *(float2*)(dst + (size_t)(row + 8) * JCOLS + col) =
                make_float2(acc[mt][nt][2], acc[mt][nt][3]);
        }
    }
}

// ---- kernel 3: out = part0 + part1 + bias (float4) ----
__global__ void __launch_bounds__(256) reduce_kernel(const float* __restrict__ bias,
                                                     float* __restrict__ out) {
    int idx = blockIdx.x * 256 + threadIdx.x;
    int o4 = (idx & 7) << 2;
    int n  = (idx >> 3) & (NN - 1);
    int b  = idx >> 16;
    size_t p = (size_t)n * JCOLS + (b << 5) + o4;
    const float4 p0 = *(const float4*)(g_part + p);
    const float4 p1 = *(const float4*)(g_part + (size_t)NN * JCOLS + p);
    const float4 bs = *(const float4*)(bias + o4);
    float4 r;
    r.x = p0.x + p1.x + bs.x;
    r.y = p0.y + p1.y + bs.y;
    r.z = p0.z + p1.z + bs.z;
    r.w = p0.w + p1.w + bs.w;
    *(float4*)(out + 4 * (size_t)idx) = r;
}

// ---------------- host ----------------
extern "C" void kernel_launch(void* const* d_in, const int* in_sizes, int n_in,
                              void* d_out, int out_size) {
    const float* x        = (const float*)d_in[0];
    const float* supports = (const float*)d_in[1];
    const float* W        = (const float*)d_in[2];
    const float* bias     = (const float*)d_in[3];
    float* out            = (float*)d_out;
    (void)in_sizes; (void)n_in; (void)out_size;

    cudaFuncSetAttribute(gemm_kernel, cudaFuncAttributeMaxDynamicSharedMemorySize, SMEM_BYTES);
    cudaFuncSetAttribute(yt_kernel, cudaFuncAttributeMaxDynamicSharedMemorySize, YT_SMEM);

    yt_kernel<<<dim3(NN / 32, NS), 256, YT_SMEM>>>(x, W);
    gemm_kernel<<<dim3(NN / BM, NS), 256, SMEM_BYTES>>>(supports);
    reduce_kernel<<<(BB * NN * COUT) / (256 * 4), 256>>>(bias, out);
}

// round 14
// speedup vs baseline: 1.1052x; 1.1052x over previous
#include <cuda_runtime.h>
#include <cuda_fp16.h>
#include <cstdint>

// ---------------- problem constants ----------------
#define BB     8
#define NN     8192
#define CIN    32
#define COUT   32
#define NS     2
#define JCOLS  256        // B * C_OUT

// ---------------- GEMM tiling ----------------
#define BM     128
#define BN     256
#define BK     32
#define NSTAGE 4
#define NKT    (NN / BK)      // 256 kt per full-K tile
// work decomposition: 128 tiles (64 n-tiles x 2 s) x 32 units of 8 kt = 4096 units
#define UPT    32             // units per tile
#define KTPU   8              // kt per unit
#define NUNITS 4096
#define MAXSLOTS 384          // 2 per CTA, supports nsm <= 192

#define PADWF  36                       // f32 A stage row stride (words)
#define PADH   40                       // fp16 row stride (halves): 80B, LDSM conflict-free
#define AF32_STG_B  (BM * PADWF * 4)    // 18432 B / stage
#define B16_STG_B   (BN * PADH * 2)     // 20480 B / stage
#define A16_BUF_B   (BM * PADH * 2)     // 10240 B
#define AF32_OFF    0
#define B16_OFF     (NSTAGE * AF32_STG_B)            // 73728
#define A16_OFF     (B16_OFF + NSTAGE * B16_STG_B)   // 155648
#define SMEM_BYTES  (A16_OFF + A16_BUF_B)            // 165888

// ---------------- scratch ----------------
__device__ __align__(1024) __half g_yt16[(size_t)NS * JCOLS * NN];     // [s][j][m] fp16
__device__ __align__(1024) float  g_frag[(size_t)MAXSLOTS * BM * JCOLS]; // partial tiles

// ---------------- PTX helpers (<= sm_80 base features only) ----------------
static __device__ __forceinline__ uint32_t smem_u32(const void* p) {
    uint32_t a;
    asm("{ .reg .u64 t; cvta.to.shared.u64 t, %1; cvt.u32.u64 %0, t; }" : "=r"(a) : "l"(p));
    return a;
}
#define CP16(dst, src) \
    asm volatile("cp.async.cg.shared.global [%0], [%1], 16;" :: "r"(dst), "l"(src) : "memory")
#define CPCOMMIT() asm volatile("cp.async.commit_group;" ::: "memory")
#define CPWAIT(n)  asm volatile("cp.async.wait_group %0;" :: "n"(n) : "memory")

#define LDSM_X4(r0, r1, r2, r3, addr) \
    asm volatile("ldmatrix.sync.aligned.m8n8.x4.shared.b16 {%0,%1,%2,%3}, [%4];" \
                 : "=r"(r0), "=r"(r1), "=r"(r2), "=r"(r3) : "r"(addr))

#define MMA_F16(d, a, b) \
    asm volatile("mma.sync.aligned.m16n8k16.row.col.f32.f16.f16.f32 " \
                 "{%0,%1,%2,%3}, {%4,%5,%6,%7}, {%8,%9}, {%0,%1,%2,%3};" \
                 : "+f"((d)[0]), "+f"((d)[1]), "+f"((d)[2]), "+f"((d)[3]) \
                 : "r"((a)[0]), "r"((a)[1]), "r"((a)[2]), "r"((a)[3]), \
                   "r"((b)[0]), "r"((b)[1]))

// ---- kernel 1: Yt[s][j][m] = sum_c x[b][m][c]*W[s][o][c]  (fp16-RN output) ----
#define YT_XS_W   (BB * 32 * CIN)
#define YT_WS_W   (COUT * 33)
#define YT_OUT_H  (JCOLS * 34)
#define YT_SMEM   ((YT_XS_W + YT_WS_W) * 4 + YT_OUT_H * 2)

__global__ void __launch_bounds__(256) yt_kernel(const float* __restrict__ x,
                                                 const float* __restrict__ W) {
    extern __shared__ float sm[];
    float* xs = sm;
    float* ws = sm + YT_XS_W;
    __half* outs = (__half*)(ws + YT_WS_W);
    int s  = blockIdx.y;
    int m0 = blockIdx.x * 32;
    int t  = threadIdx.x;

    for (int i = t; i < COUT * CIN; i += 256)
        ws[(i >> 5) * 33 + (i & 31)] = W[s * COUT * CIN + i];
    for (int i = t; i < YT_XS_W; i += 256) {
        int b = i >> 10;
        xs[i] = x[(size_t)b * NN * CIN + (size_t)m0 * CIN + (i & 1023)];
    }
    __syncthreads();

    int b = t >> 5, o = t & 31;
    float wr[32];
#pragma unroll
    for (int c = 0; c < 32; ++c) wr[c] = ws[o * 33 + c];

    const float4* xr = (const float4*)(xs + b * 1024);
    __half* orow = outs + t * 34;
    for (int m = 0; m < 32; ++m) {
        float acc = 0.f;
#pragma unroll
        for (int q = 0; q < 8; ++q) {
            float4 v = xr[m * 8 + q];
            acc = fmaf(v.x, wr[q * 4 + 0], acc);
            acc = fmaf(v.y, wr[q * 4 + 1], acc);
            acc = fmaf(v.z, wr[q * 4 + 2], acc);
            acc = fmaf(v.w, wr[q * 4 + 3], acc);
        }
        orow[m] = __float2half_rn(acc);
    }
    __syncthreads();

    uint32_t* dst32 = (uint32_t*)g_yt16;
    for (int i = t; i < JCOLS * 16; i += 256) {
        int j = i >> 4, mp = i & 15;
        uint32_t v = *(const uint32_t*)(outs + j * 34 + 2 * mp);
        dst32[((((size_t)s * JCOLS + j) * NN + m0) >> 1) + mp] = v;
    }
}

// ---- kernel 2: persistent fp16 GEMM over all SMs, fragment outputs ----
__global__ void __launch_bounds__(256, 1) gemm_kernel(const float* __restrict__ supports) {
    extern __shared__ char smc[];
    int tid  = threadIdx.x;
    int lane = tid & 31, w = tid >> 5;
    int wm = w >> 2, wn = w & 3;              // 2 (M) x 4 (N) warps, 64x64 each
    uint32_t smb = smem_u32(smc);

    uint32_t a_row  = (uint32_t)(lane & 15);
    uint32_t a_koff = (uint32_t)((lane >> 4) << 3);
    uint32_t b_row  = (uint32_t)((lane & 7) + ((lane >> 4) << 3));
    uint32_t b_koff = (uint32_t)(((lane >> 3) & 1) << 3);
    int cr = tid >> 1, ch = tid & 1;          // convert mapping

    int c   = blockIdx.x;
    int nsm = gridDim.x;
    int u0 = (c * NUNITS) / nsm;
    int u1 = ((c + 1) * NUNITS) / nsm;
    int slot = 2 * c;

    float acc[4][8][4];
#pragma unroll
    for (int mt = 0; mt < 4; ++mt)
#pragma unroll
        for (int nt = 0; nt < 8; ++nt)
#pragma unroll
            for (int r = 0; r < 4; ++r) acc[mt][nt][r] = 0.f;

    int uc = u0;
    while (uc < u1) {
        int t    = uc >> 5;                       // tile id: s*64 + ntile
        int uend = min(u1, (t + 1) << 5);
        int kt0g = (uc & (UPT - 1)) * KTPU;       // tile-local kt start
        int nkt  = (uend - uc) * KTPU;            // 8..256
        int s  = t >> 6, nt0 = t & 63;

        const float*  Abase = supports + ((size_t)s * NN + (size_t)nt0 * BM) * NN
                                       + (size_t)kt0g * BK;
        const __half* Bbase = g_yt16 + (size_t)s * JCOLS * NN + (size_t)kt0g * BK;

        __syncthreads();                          // smem stages/A16 free of prior readers

        // prologue: stages 0..2
#pragma unroll
        for (int p = 0; p < NSTAGE - 1; ++p) {
#pragma unroll
            for (int i = 0; i < 8; ++i) {
                int idx = i * 256 + tid;
                if (idx < 1024) {                 // A f32
                    int r = idx >> 3, cc = idx & 7;
                    CP16(smb + AF32_OFF + p * AF32_STG_B + (uint32_t)(r * PADWF + cc * 4) * 4,
                         Abase + (size_t)r * NN + (size_t)p * BK + cc * 4);
                } else {                          // B fp16
                    int bi = idx - 1024;
                    int r = bi >> 2, cc = bi & 3;
                    CP16(smb + B16_OFF + p * B16_STG_B + (uint32_t)(r * PADH * 2 + cc * 16),
                         Bbase + (size_t)r * NN + (size_t)p * BK + cc * 8);
                }
            }
            CPCOMMIT();
        }

        for (int kt = 0; kt < nkt; ++kt) {
            CPWAIT(2);
            __syncthreads();                      // stage kt ready for all

            // convert A f32 stage kt -> A16 (single buffer)
            {
                const float4* af = (const float4*)(smc + AF32_OFF + (kt & 3) * AF32_STG_B);
                int fi = cr * (PADWF / 4) + ch * 4;
                float4 v0 = af[fi], v1 = af[fi + 1], v2 = af[fi + 2], v3 = af[fi + 3];
                __half2 h[8];
                h[0] = __floats2half2_rn(v0.x, v0.y); h[1] = __floats2half2_rn(v0.z, v0.w);
                h[2] = __floats2half2_rn(v1.x, v1.y); h[3] = __floats2half2_rn(v1.z, v1.w);
                h[4] = __floats2half2_rn(v2.x, v2.y); h[5] = __floats2half2_rn(v2.z, v2.w);
                h[6] = __floats2half2_rn(v3.x, v3.y); h[7] = __floats2half2_rn(v3.z, v3.w);
                uint4* dst = (uint4*)(smc + A16_OFF + (cr * PADH + ch * 16) * 2);
                dst[0] = *(uint4*)&h[0];
                dst[1] = *(uint4*)&h[4];
            }

            int kn = kt + NSTAGE - 1;
            if (kn < nkt) {                       // refill slot (kn&3), dead since kt-1
#pragma unroll
                for (int i = 0; i < 8; ++i) {
                    int idx = i * 256 + tid;
                    if (idx < 1024) {
                        int r = idx >> 3, cc = idx & 7;
                        CP16(smb + AF32_OFF + (kn & 3) * AF32_STG_B + (uint32_t)(r * PADWF + cc * 4) * 4,
                             Abase + (size_t)r * NN + (size_t)kn * BK + cc * 4);
                    } else {
                        int bi = idx - 1024;
                        int r = bi >> 2, cc = bi & 3;
                        CP16(smb + B16_OFF + (kn & 3) * B16_STG_B + (uint32_t)(r * PADH * 2 + cc * 16),
                             Bbase + (size_t)r * NN + (size_t)kn * BK + cc * 8);
                    }
                }
            }
            CPCOMMIT();                           // unconditional: keeps group count = 3
            __syncthreads();                      // A16 visible

            uint32_t A16 = smb + A16_OFF;
            uint32_t B16 = smb + B16_OFF + (kt & 3) * B16_STG_B;
#pragma unroll
            for (int kc = 0; kc < 2; ++kc) {
                uint32_t af4[4][4], bf[8][2];
#pragma unroll
                for (int mt = 0; mt < 4; ++mt) {
                    uint32_t ad = A16 + (((uint32_t)(wm * 64 + mt * 16) + a_row) * PADH
                                         + kc * 16 + a_koff) * 2;
                    LDSM_X4(af4[mt][0], af4[mt][1], af4[mt][2], af4[mt][3], ad);
                }
#pragma unroll
                for (int np = 0; np < 4; ++np) {
                    uint32_t bd = B16 + (((uint32_t)(wn * 64 + np * 16) + b_row) * PADH
                                         + kc * 16 + b_koff) * 2;
                    LDSM_X4(bf[2 * np][0], bf[2 * np][1], bf[2 * np + 1][0], bf[2 * np + 1][1], bd);
                }
#pragma unroll
                for (int mt = 0; mt < 4; ++mt)
#pragma unroll
                    for (int nt = 0; nt < 8; ++nt)
                        MMA_F16(acc[mt][nt], af4[mt], bf[nt]);
            }
        }

        // flush fragment, reset acc
        int g = lane >> 2, t4 = lane & 3;
        float* dstf = g_frag + (size_t)slot * (BM * JCOLS);
#pragma unroll
        for (int mt = 0; mt < 4; ++mt) {
#pragma unroll
            for (int nt = 0; nt < 8; ++nt) {
                int row = wm * 64 + mt * 16 + g;
                int col = wn * 64 + nt * 8 + 2 * t4;
                *(float2*)(dstf + (size_t)row * JCOLS + col) =
                    make_float2(acc[mt][nt][0], acc[mt][nt][1]);
                *(float2*)(dstf + (size_t)(row + 8) * JCOLS + col) =
                    make_float2(acc[mt][nt][2], acc[mt][nt][3]);
#pragma unroll
                for (int r = 0; r < 4; ++r) acc[mt][nt][r] = 0.f;
            }
        }
        uc = uend;
        ++slot;
    }
}

// ---- kernel 3: out = sum(fragments) + bias ----
__global__ void __launch_bounds__(256) reduce_kernel(const float* __restrict__ bias,
                                                     float* __restrict__ out, int nsm) {
    int idx = blockIdx.x * 256 + threadIdx.x;   // 2^19 threads x 4 elems
    int o4 = (idx & 7) << 2;
    int n  = (idx >> 3) & (NN - 1);
    int b  = idx >> 16;
    int ntile = n >> 7;
    int row   = n & 127;
    int col   = (b << 5) + o4;

    const float4 bs = *(const float4*)(bias + o4);
    float rx = bs.x, ry = bs.y, rz = bs.z, rw = bs.w;

#pragma unroll
    for (int s = 0; s < NS; ++s) {
        int t  = s * 64 + ntile;
        int us = t << 5;                        // first unit of tile
        int cg = (us * nsm) >> 12;              // ~ CTA containing unit us
        int clo = cg > 0 ? cg - 1 : 0;
        int chi = cg + 3; if (chi >= nsm) chi = nsm - 1;
        for (int cc = clo; cc <= chi; ++cc) {
            int u0c = (cc * NUNITS) / nsm;
            int u1c = ((cc + 1) * NUNITS) / nsm;
            int lo = u0c > us ? u0c : us;
            int hi = u1c < us + 32 ? u1c : us + 32;
            if (lo < hi) {
                int slot = 2 * cc + (((u0c >> 5) == t) ? 0 : 1);
                const float4 f = *(const float4*)(g_frag + (size_t)slot * (BM * JCOLS)
                                                  + (size_t)row * JCOLS + col);
                rx += f.x; ry += f.y; rz += f.z; rw += f.w;
            }
        }
    }
    float4 r; r.x = rx; r.y = ry; r.z = rz; r.w = rw;
    *(float4*)(out + 4 * (size_t)idx) = r;
}

// ---------------- host ----------------
extern "C" void kernel_launch(void* const* d_in, const int* in_sizes, int n_in,
                              void* d_out, int out_size) {
    const float* x        = (const float*)d_in[0];
    const float* supports = (const float*)d_in[1];
    const float* W        = (const float*)d_in[2];
    const float* bias     = (const float*)d_in[3];
    float* out            = (float*)d_out;
    (void)in_sizes; (void)n_in; (void)out_size;

    int nsm = 148;
    cudaDeviceGetAttribute(&nsm, cudaDevAttrMultiProcessorCount, 0);
    if (nsm < 1) nsm = 148;
    if (nsm > MAXSLOTS / 2) nsm = MAXSLOTS / 2;

    cudaFuncSetAttribute(gemm_kernel, cudaFuncAttributeMaxDynamicSharedMemorySize, SMEM_BYTES);
    cudaFuncSetAttribute(yt_kernel, cudaFuncAttributeMaxDynamicSharedMemorySize, YT_SMEM);

    yt_kernel<<<dim3(NN / 32, NS), 256, YT_SMEM>>>(x, W);
    gemm_kernel<<<nsm, 256, SMEM_BYTES>>>(supports);
    reduce_kernel<<<(BB * NN * COUT) / (256 * 4), 256>>>(bias, out, nsm);
}

// round 15
// speedup vs baseline: 1.1138x; 1.0078x over previous
#include <cuda_runtime.h>
#include <cuda_fp16.h>
#include <cstdint>

// ---------------- problem constants ----------------
#define BB     8
#define NN     8192
#define CIN    32
#define COUT   32
#define NS     2
#define JCOLS  256        // B * C_OUT

// ---------------- GEMM tiling ----------------
#define BM     128
#define BN     256
#define BK     32
#define NSTAGE 4
#define NKT    (NN / BK)
// work decomposition: 128 tiles (64 n-tiles x 2 s) x 32 units of 8 kt = 4096 units
#define UPT    32
#define KTPU   8
#define NUNITS 4096
#define MAXSLOTS 384          // 2 per CTA, supports nsm <= 192

#define PADWF  36                       // f32 A stage row stride (words)
#define PADH   40                       // fp16 row stride (halves): 80B, LDSM conflict-free
#define AF32_STG_B  (BM * PADWF * 4)    // 18432 B / stage
#define B16_STG_B   (BN * PADH * 2)     // 20480 B / stage
#define A16_STG_B   (BM * PADH * 2)     // 10240 B / stage
#define AF32_OFF    0
#define B16_OFF     (NSTAGE * AF32_STG_B)            // 73728
#define A16_OFF     (B16_OFF + NSTAGE * B16_STG_B)   // 155648
#define SMEM_BYTES  (A16_OFF + NSTAGE * A16_STG_B)   // 196608

// ---------------- scratch ----------------
__device__ __align__(1024) __half g_yt16[(size_t)NS * JCOLS * NN];       // [s][j][m] fp16
__device__ __align__(1024) float  g_frag[(size_t)MAXSLOTS * BM * JCOLS]; // partial tiles

// ---------------- PTX helpers (<= sm_80 base features only) ----------------
static __device__ __forceinline__ uint32_t smem_u32(const void* p) {
    uint32_t a;
    asm("{ .reg .u64 t; cvta.to.shared.u64 t, %1; cvt.u32.u64 %0, t; }" : "=r"(a) : "l"(p));
    return a;
}
#define CP16(dst, src) \
    asm volatile("cp.async.cg.shared.global [%0], [%1], 16;" :: "r"(dst), "l"(src) : "memory")
#define CPCOMMIT() asm volatile("cp.async.commit_group;" ::: "memory")
#define CPWAIT(n)  asm volatile("cp.async.wait_group %0;" :: "n"(n) : "memory")

#define LDSM_X4(r0, r1, r2, r3, addr) \
    asm volatile("ldmatrix.sync.aligned.m8n8.x4.shared.b16 {%0,%1,%2,%3}, [%4];" \
                 : "=r"(r0), "=r"(r1), "=r"(r2), "=r"(r3) : "r"(addr))

#define MMA_F16(d, a, b) \
    asm volatile("mma.sync.aligned.m16n8k16.row.col.f32.f16.f16.f32 " \
                 "{%0,%1,%2,%3}, {%4,%5,%6,%7}, {%8,%9}, {%0,%1,%2,%3};" \
                 : "+f"((d)[0]), "+f"((d)[1]), "+f"((d)[2]), "+f"((d)[3]) \
                 : "r"((a)[0]), "r"((a)[1]), "r"((a)[2]), "r"((a)[3]), \
                   "r"((b)[0]), "r"((b)[1]))

// convert one f32 A stage slot -> fp16 A16 slot (per-thread: half a row, 16 floats)
static __device__ __forceinline__ void convert_a(char* smc, int slot, int cr, int ch) {
    const float4* af = (const float4*)(smc + AF32_OFF + slot * AF32_STG_B);
    int fi = cr * (PADWF / 4) + ch * 4;
    float4 v0 = af[fi], v1 = af[fi + 1], v2 = af[fi + 2], v3 = af[fi + 3];
    __half2 h[8];
    h[0] = __floats2half2_rn(v0.x, v0.y); h[1] = __floats2half2_rn(v0.z, v0.w);
    h[2] = __floats2half2_rn(v1.x, v1.y); h[3] = __floats2half2_rn(v1.z, v1.w);
    h[4] = __floats2half2_rn(v2.x, v2.y); h[5] = __floats2half2_rn(v2.z, v2.w);
    h[6] = __floats2half2_rn(v3.x, v3.y); h[7] = __floats2half2_rn(v3.z, v3.w);
    uint4* dst = (uint4*)(smc + A16_OFF + slot * A16_STG_B + (cr * PADH + ch * 16) * 2);
    dst[0] = *(uint4*)&h[0];
    dst[1] = *(uint4*)&h[4];
}

// ---- kernel 1: Yt[s][j][m] = sum_c x[b][m][c]*W[s][o][c]  (fp16-RN output) ----
#define YT_XS_W   (BB * 32 * CIN)
#define YT_WS_W   (COUT * 33)
#define YT_OUT_H  (JCOLS * 34)
#define YT_SMEM   ((YT_XS_W + YT_WS_W) * 4 + YT_OUT_H * 2)

__global__ void __launch_bounds__(256) yt_kernel(const float* __restrict__ x,
                                                 const float* __restrict__ W) {
    extern __shared__ float sm[];
    float* xs = sm;
    float* ws = sm + YT_XS_W;
    __half* outs = (__half*)(ws + YT_WS_W);
    int s  = blockIdx.y;
    int m0 = blockIdx.x * 32;
    int t  = threadIdx.x;

    for (int i = t; i < COUT * CIN; i += 256)
        ws[(i >> 5) * 33 + (i & 31)] = W[s * COUT * CIN + i];
    for (int i = t; i < YT_XS_W; i += 256) {
        int b = i >> 10;
        xs[i] = x[(size_t)b * NN * CIN + (size_t)m0 * CIN + (i & 1023)];
    }
    __syncthreads();

    int b = t >> 5, o = t & 31;
    float wr[32];
#pragma unroll
    for (int c = 0; c < 32; ++c) wr[c] = ws[o * 33 + c];

    const float4* xr = (const float4*)(xs + b * 1024);
    __half* orow = outs + t * 34;
    for (int m = 0; m < 32; ++m) {
        float acc = 0.f;
#pragma unroll
        for (int q = 0; q < 8; ++q) {
            float4 v = xr[m * 8 + q];
            acc = fmaf(v.x, wr[q * 4 + 0], acc);
            acc = fmaf(v.y, wr[q * 4 + 1], acc);
            acc = fmaf(v.z, wr[q * 4 + 2], acc);
            acc = fmaf(v.w, wr[q * 4 + 3], acc);
        }
        orow[m] = __float2half_rn(acc);
    }
    __syncthreads();

    uint32_t* dst32 = (uint32_t*)g_yt16;
    for (int i = t; i < JCOLS * 16; i += 256) {
        int j = i >> 4, mp = i & 15;
        uint32_t v = *(const uint32_t*)(outs + j * 34 + 2 * mp);
        dst32[((((size_t)s * JCOLS + j) * NN + m0) >> 1) + mp] = v;
    }
}

// ---- kernel 2: persistent fp16 GEMM, single-barrier pipelined A conversion ----
__global__ void __launch_bounds__(256, 1) gemm_kernel(const float* __restrict__ supports) {
    extern __shared__ char smc[];
    int tid  = threadIdx.x;
    int lane = tid & 31, w = tid >> 5;
    int wm = w >> 2, wn = w & 3;              // 2 (M) x 4 (N) warps, 64x64 each
    uint32_t smb = smem_u32(smc);

    uint32_t a_row  = (uint32_t)(lane & 15);
    uint32_t a_koff = (uint32_t)((lane >> 4) << 3);
    uint32_t b_row  = (uint32_t)((lane & 7) + ((lane >> 4) << 3));
    uint32_t b_koff = (uint32_t)(((lane >> 3) & 1) << 3);
    int cr = tid >> 1, ch = tid & 1;

    int c   = blockIdx.x;
    int nsm = gridDim.x;
    int u0 = (c * NUNITS) / nsm;
    int u1 = ((c + 1) * NUNITS) / nsm;
    int slot = 2 * c;

    float acc[4][8][4];
#pragma unroll
    for (int mt = 0; mt < 4; ++mt)
#pragma unroll
        for (int nt = 0; nt < 8; ++nt)
#pragma unroll
            for (int r = 0; r < 4; ++r) acc[mt][nt][r] = 0.f;

    int uc = u0;
    while (uc < u1) {
        int t    = uc >> 5;                       // tile id: s*64 + ntile
        int uend = min(u1, (t + 1) << 5);
        int kt0g = (uc & (UPT - 1)) * KTPU;
        int nkt  = (uend - uc) * KTPU;
        int s  = t >> 6, nt0 = t & 63;

        const float*  Abase = supports + ((size_t)s * NN + (size_t)nt0 * BM) * NN
                                       + (size_t)kt0g * BK;
        const __half* Bbase = g_yt16 + (size_t)s * JCOLS * NN + (size_t)kt0g * BK;

        __syncthreads();                          // prior readers of smem done

        // prologue: stages 0..2
#pragma unroll
        for (int p = 0; p < NSTAGE - 1; ++p) {
#pragma unroll
            for (int i = 0; i < 8; ++i) {
                int idx = i * 256 + tid;
                if (idx < 1024) {                 // A f32
                    int r = idx >> 3, cc = idx & 7;
                    CP16(smb + AF32_OFF + p * AF32_STG_B + (uint32_t)(r * PADWF + cc * 4) * 4,
                         Abase + (size_t)r * NN + (size_t)p * BK + cc * 4);
                } else {                          // B fp16
                    int bi = idx - 1024;
                    int r = bi >> 2, cc = bi & 3;
                    CP16(smb + B16_OFF + p * B16_STG_B + (uint32_t)(r * PADH * 2 + cc * 16),
                         Bbase + (size_t)r * NN + (size_t)p * BK + cc * 8);
                }
            }
            CPCOMMIT();
        }

        // prologue convert: stage 0 -> A16 slot 0
        CPWAIT(2);
        __syncthreads();
        convert_a(smc, 0, cr, ch);

        for (int kt = 0; kt < nkt; ++kt) {
            CPWAIT(1);                            // drains stage kt+1 (this thread)
            __syncthreads();                      // publish A16[kt&3], stage kt+1, slot deaths

            int kn = kt + NSTAGE - 1;
            if (kn < nkt) {                       // refill slot (kn&3) = (kt-1)&3, dead
#pragma unroll
                for (int i = 0; i < 8; ++i) {
                    int idx = i * 256 + tid;
                    if (idx < 1024) {
                        int r = idx >> 3, cc = idx & 7;
                        CP16(smb + AF32_OFF + (kn & 3) * AF32_STG_B + (uint32_t)(r * PADWF + cc * 4) * 4,
                             Abase + (size_t)r * NN + (size_t)kn * BK + cc * 4);
                    } else {
                        int bi = idx - 1024;
                        int r = bi >> 2, cc = bi & 3;
                        CP16(smb + B16_OFF + (kn & 3) * B16_STG_B + (uint32_t)(r * PADH * 2 + cc * 16),
                             Bbase + (size_t)r * NN + (size_t)kn * BK + cc * 8);
                    }
                }
            }
            CPCOMMIT();                           // unconditional: group-count invariant

            // convert stage kt+1 -> A16[(kt+1)&3]; overlaps MMAs below (FMA pipe)
            if (kt + 1 < nkt)
                convert_a(smc, (kt + 1) & 3, cr, ch);

            uint32_t A16 = smb + A16_OFF + (kt & 3) * A16_STG_B;
            uint32_t B16 = smb + B16_OFF + (kt & 3) * B16_STG_B;
#pragma unroll
            for (int kc = 0; kc < 2; ++kc) {
                uint32_t af4[4][4], bf[8][2];
#pragma unroll
                for (int mt = 0; mt < 4; ++mt) {
                    uint32_t ad = A16 + (((uint32_t)(wm * 64 + mt * 16) + a_row) * PADH
                                         + kc * 16 + a_koff) * 2;
                    LDSM_X4(af4[mt][0], af4[mt][1], af4[mt][2], af4[mt][3], ad);
                }
#pragma unroll
                for (int np = 0; np < 4; ++np) {
                    uint32_t bd = B16 + (((uint32_t)(wn * 64 + np * 16) + b_row) * PADH
                                         + kc * 16 + b_koff) * 2;
                    LDSM_X4(bf[2 * np][0], bf[2 * np][1], bf[2 * np + 1][0], bf[2 * np + 1][1], bd);
                }
#pragma unroll
                for (int mt = 0; mt < 4; ++mt)
#pragma unroll
                    for (int nt = 0; nt < 8; ++nt)
                        MMA_F16(acc[mt][nt], af4[mt], bf[nt]);
            }
        }

        // flush fragment, reset acc
        int g = lane >> 2, t4 = lane & 3;
        float* dstf = g_frag + (size_t)slot * (BM * JCOLS);
#pragma unroll
        for (int mt = 0; mt < 4; ++mt) {
#pragma unroll
            for (int nt = 0; nt < 8; ++nt) {
                int row = wm * 64 + mt * 16 + g;
                int col = wn * 64 + nt * 8 + 2 * t4;
                *(float2*)(dstf + (size_t)row * JCOLS + col) =
                    make_float2(acc[mt][nt][0], acc[mt][nt][1]);
                *(float2*)(dstf + (size_t)(row + 8) * JCOLS + col) =
                    make_float2(acc[mt][nt][2], acc[mt][nt][3]);
#pragma unroll
                for (int r = 0; r < 4; ++r) acc[mt][nt][r] = 0.f;
            }
        }
        uc = uend;
        ++slot;
    }
}

// ---- kernel 3: out = sum(fragments) + bias ----
__global__ void __launch_bounds__(256) reduce_kernel(const float* __restrict__ bias,
                                                     float* __restrict__ out, int nsm) {
    int idx = blockIdx.x * 256 + threadIdx.x;
    int o4 = (idx & 7) << 2;
    int n  = (idx >> 3) & (NN - 1);
    int b  = idx >> 16;
    int ntile = n >> 7;
    int row   = n & 127;
    int col   = (b << 5) + o4;

    const float4 bs = *(const float4*)(bias + o4);
    float rx = bs.x, ry = bs.y, rz = bs.z, rw = bs.w;

#pragma unroll
    for (int s = 0; s < NS; ++s) {
        int t  = s * 64 + ntile;
        int us = t << 5;
        int cg = (us * nsm) >> 12;
        int clo = cg > 0 ? cg - 1 : 0;
        int chi = cg + 3; if (chi >= nsm) chi = nsm - 1;
        for (int cc = clo; cc <= chi; ++cc) {
            int u0c = (cc * NUNITS) / nsm;
            int u1c = ((cc + 1) * NUNITS) / nsm;
            int lo = u0c > us ? u0c : us;
            int hi = u1c < us + 32 ? u1c : us + 32;
            if (lo < hi) {
                int slot = 2 * cc + (((u0c >> 5) == t) ? 0 : 1);
                const float4 f = *(const float4*)(g_frag + (size_t)slot * (BM * JCOLS)
                                                  + (size_t)row * JCOLS + col);
                rx += f.x; ry += f.y; rz += f.z; rw += f.w;
            }
        }
    }
    float4 r; r.x = rx; r.y = ry; r.z = rz; r.w = rw;
    *(float4*)(out + 4 * (size_t)idx) = r;
}

// ---------------- host ----------------
extern "C" void kernel_launch(void* const* d_in, const int* in_sizes, int n_in,
                              void* d_out, int out_size) {
    const float* x        = (const float*)d_in[0];
    const float* supports = (const float*)d_in[1];
    const float* W        = (const float*)d_in[2];
    const float* bias     = (const float*)d_in[3];
    float* out            = (float*)d_out;
    (void)in_sizes; (void)n_in; (void)out_size;

    int nsm = 148;
    cudaDeviceGetAttribute(&nsm, cudaDevAttrMultiProcessorCount, 0);
    if (nsm < 1) nsm = 148;
    if (nsm > MAXSLOTS / 2) nsm = MAXSLOTS / 2;

    cudaFuncSetAttribute(gemm_kernel, cudaFuncAttributeMaxDynamicSharedMemorySize, SMEM_BYTES);
    cudaFuncSetAttribute(yt_kernel, cudaFuncAttributeMaxDynamicSharedMemorySize, YT_SMEM);

    yt_kernel<<<dim3(NN / 32, NS), 256, YT_SMEM>>>(x, W);
    gemm_kernel<<<nsm, 256, SMEM_BYTES>>>(supports);
    reduce_kernel<<<(BB * NN * COUT) / (256 * 4), 256>>>(bias, out, nsm);
}